// round 12
// baseline (speedup 1.0000x reference)
#include <cuda_runtime.h>
#include <math.h>

#define B_ 4
#define T_ 256
#define D_ 1024
#define H_ 16
#define DH_ 64
#define L_ 4
#define V_ 32000
#define FF_ 4096
#define M_ 767            // 3*T - 1
#define NR_ (B_*M_)       // 3068
#define SLD_ 768          // padded score row stride

// smem layout constants for gemm: per matrix per stage = 4 k-slices
#define SS_ 1032          // slice stride in floats (128*8 + 8 pad)
#define MATS_ (4*SS_)     // 4128 floats per matrix per stage
#define GEMM_SMEM_BYTES (4*MATS_*4)   // A[2] + B[2] stages = 66048 B

// ---------------- scratch (static device globals; no allocation) ----------------
__device__ float g_x[NR_*D_];
__device__ float g_h[NR_*D_];
__device__ float g_q[NR_*D_];
__device__ float g_k[NR_*D_];
__device__ float g_v[NR_*D_];
__device__ float g_vt[B_*H_*DH_*SLD_];         // V transposed per (b,h): [64][768]
__device__ float g_y[NR_*D_];
__device__ float g_ffn[NR_*FF_];
__device__ float g_s[(size_t)B_*H_*M_*SLD_];   // attention scores/probs
__device__ float g_hf[B_*T_*D_];

// ---------------- helpers ----------------
__device__ __forceinline__ float blockReduceSum256(float val) {
    __shared__ float sb[8];
    int lane = threadIdx.x & 31, wid = threadIdx.x >> 5;
    #pragma unroll
    for (int o = 16; o; o >>= 1) val += __shfl_xor_sync(0xffffffffu, val, o);
    if (lane == 0) sb[wid] = val;
    __syncthreads();
    float r = 0.f;
    #pragma unroll
    for (int i = 0; i < 8; i++) r += sb[i];
    __syncthreads();
    return r;
}

__device__ __forceinline__ float cvt_tf32(float x) {
    float r;
    asm("cvt.rna.tf32.f32 %0, %1;" : "=f"(r) : "f"(x));
    return r;
}

__device__ __forceinline__ void mma_tf32(float* d, const unsigned* a, const unsigned* b) {
    asm volatile(
        "mma.sync.aligned.m16n8k8.row.col.f32.tf32.tf32.f32 "
        "{%0,%1,%2,%3},{%4,%5,%6,%7},{%8,%9},{%0,%1,%2,%3};"
        : "+f"(d[0]), "+f"(d[1]), "+f"(d[2]), "+f"(d[3])
        : "r"(a[0]), "r"(a[1]), "r"(a[2]), "r"(a[3]), "r"(b[0]), "r"(b[1]));
}

// ---------------- embedding ----------------
__global__ __launch_bounds__(256) void embed_kernel(
    const float* __restrict__ states, const int* __restrict__ actions,
    const float* __restrict__ rtg, const int* __restrict__ tsteps,
    const float* __restrict__ pe, const float* __restrict__ gpe,
    const float* __restrict__ Ws, const float* __restrict__ bs,
    const float* __restrict__ Wr, const float* __restrict__ br,
    const float* __restrict__ aemb, float* __restrict__ xout)
{
    int m = blockIdx.x, b = blockIdx.y;
    int i = m / 3, r = m - 3 * i;
    int d = threadIdx.x * 4;
    float t0, t1, t2, t3;
    if (r == 2) {
        long a = actions[b * T_ + i + 1];
        const float* ap = aemb + a * D_ + d;
        t0 = tanhf(ap[0]); t1 = tanhf(ap[1]); t2 = tanhf(ap[2]); t3 = tanhf(ap[3]);
    } else {
        float xval = (r == 0) ? rtg[b * T_ + i] : states[b * T_ + i];
        const float* Wp = (r == 0) ? Wr : Ws;
        const float* bp = (r == 0) ? br : bs;
        t0 = tanhf(xval * Wp[d+0] + bp[d+0]);
        t1 = tanhf(xval * Wp[d+1] + bp[d+1]);
        t2 = tanhf(xval * Wp[d+2] + bp[d+2]);
        t3 = tanhf(xval * Wp[d+3] + bp[d+3]);
    }
    int ts = tsteps[b];
    const float* gp = gpe + (long)ts * D_ + d;
    const float* pp = pe + (long)m * D_ + d;
    float* xp = xout + ((long)b * M_ + m) * D_ + d;
    xp[0] = t0 + gp[0] + pp[0];
    xp[1] = t1 + gp[1] + pp[1];
    xp[2] = t2 + gp[2] + pp[2];
    xp[3] = t3 + gp[3] + pp[3];
}

// ---------------- layernorm ----------------
__global__ __launch_bounds__(256) void ln_kernel(const float* __restrict__ in,
        const float* __restrict__ g, const float* __restrict__ bb,
        float* __restrict__ out)
{
    long row = blockIdx.x;
    int d = threadIdx.x * 4;
    float4 xv = *(const float4*)(in + row * D_ + d);
    float mean = blockReduceSum256(xv.x + xv.y + xv.z + xv.w) * (1.f / D_);
    float a0 = xv.x - mean, a1 = xv.y - mean, a2 = xv.z - mean, a3 = xv.w - mean;
    float var = blockReduceSum256(a0*a0 + a1*a1 + a2*a2 + a3*a3) * (1.f / D_);
    float inv = rsqrtf(var + 1e-5f);
    float4 gv = *(const float4*)(g + d);
    float4 bv = *(const float4*)(bb + d);
    float4 o;
    o.x = a0 * inv * gv.x + bv.x;
    o.y = a1 * inv * gv.y + bv.y;
    o.z = a2 * inv * gv.z + bv.z;
    o.w = a3 * inv * gv.w + bv.w;
    *(float4*)(out + row * D_ + d) = o;
}

__global__ __launch_bounds__(256) void gatherln_kernel(const float* __restrict__ in,
        const float* __restrict__ g, const float* __restrict__ bb,
        float* __restrict__ out)
{
    int n = blockIdx.x;
    int b = n >> 8, i = n & 255;
    long src = ((long)b * M_ + 1 + 3 * i) * D_;
    int d = threadIdx.x * 4;
    float4 xv = *(const float4*)(in + src + d);
    float mean = blockReduceSum256(xv.x + xv.y + xv.z + xv.w) * (1.f / D_);
    float a0 = xv.x - mean, a1 = xv.y - mean, a2 = xv.z - mean, a3 = xv.w - mean;
    float var = blockReduceSum256(a0*a0 + a1*a1 + a2*a2 + a3*a3) * (1.f / D_);
    float inv = rsqrtf(var + 1e-5f);
    float4 gv = *(const float4*)(g + d);
    float4 bv = *(const float4*)(bb + d);
    float4 o;
    o.x = a0 * inv * gv.x + bv.x;
    o.y = a1 * inv * gv.y + bv.y;
    o.z = a2 * inv * gv.z + bv.z;
    o.w = a3 * inv * gv.w + bv.w;
    *(float4*)(out + (long)n * D_ + d) = o;
}

// ---------------- V transpose: V[b][k][h*64+n] -> Vt[(b*H+h)][n][k], k-stride 768 ----------------
__global__ __launch_bounds__(256) void transpose_v(const float* __restrict__ V,
                                                   float* __restrict__ Vt)
{
    __shared__ float tile[32][33];
    int k0 = blockIdx.x * 32, n0 = blockIdx.y * 32, b = blockIdx.z;
    int tx = threadIdx.x & 31, ty = threadIdx.x >> 5;   // 32x8
    #pragma unroll
    for (int i = 0; i < 4; i++) {
        int k = k0 + ty + 8 * i;
        tile[ty + 8 * i][tx] = (k < M_) ? V[((long)b * M_ + k) * D_ + n0 + tx] : 0.f;
    }
    __syncthreads();
    #pragma unroll
    for (int i = 0; i < 4; i++) {
        int n = n0 + ty + 8 * i;
        int h = n >> 6, nn = n & 63;
        int k = k0 + tx;
        if (k < M_)
            Vt[(((long)b * H_ + h) * DH_ + nn) * SLD_ + k] = tile[tx][ty + 8 * i];
    }
}

// ---------------- tf32 tensor-core NT GEMM (double-buffered, k-slice smem) ----------------
// C[n,o] = act(scale * sum_k A[n,k] * B[o,k] + bias[o]) + res
// mode: 0 = plain, 1 = causal tile-skip (QK^T), 2 = K truncated to bm0+128 (PV)
// triple: z in {0,1,2} selects (Bw,bias,C) / (Bw1,bias1,C1) / (Bw2,bias2,C2)
__global__ __launch_bounds__(256, 2) void gemm_tf32(
    const float* __restrict__ A, int lda,
    const float* __restrict__ Bw, int ldb,
    float* __restrict__ C, int ldc,
    int N, int O, int K,
    const float* __restrict__ bias,
    const float* __restrict__ res,
    float scale, int act, int mode,
    int zdiv, long sA1, long sA2, long sB1, long sB2, long sC1, long sC2,
    const float* __restrict__ Bw1, const float* __restrict__ Bw2,
    const float* __restrict__ bias1, const float* __restrict__ bias2,
    float* __restrict__ C1, float* __restrict__ C2, int triple)
{
    extern __shared__ float sm[];
    int bm0 = blockIdx.y * 128;
    int bn0 = blockIdx.x * 128;
    if (mode == 1 && bn0 >= bm0 + 128) return;
    int z = blockIdx.z;
    if (triple) {
        if (z == 1) { Bw = Bw1; bias = bias1; C = C1; }
        else if (z == 2) { Bw = Bw2; bias = bias2; C = C2; }
    } else {
        int zq = z / zdiv, zr = z - zq * zdiv;
        A  += (long)zq * sA1 + (long)zr * sA2;
        Bw += (long)zq * sB1 + (long)zr * sB2;
        long offC = (long)zq * sC1 + (long)zr * sC2;
        C += offC;
        if (res) res += offC;
    }

    int Keff = (mode == 2) ? min(K, bm0 + 128) : K;

    float* As = sm;               // 2 stages x MATS_
    float* Bs = sm + 2 * MATS_;   // 2 stages x MATS_

    int tid = threadIdx.x;
    // loader mapping: 256 threads, 4 float4 per matrix per tile
    int lm = tid >> 3;               // 0..31 (row group)
    int lk = (tid & 7) << 2;         // 0..28 (k offset, 4-aligned)
    int lslice = lk >> 3;            // 0..3
    int lpos   = lk & 7;             // 0 or 4
    const float* aptr = A + (long)(bm0 + lm) * lda + lk;
    const float* bptr = Bw + (long)(bn0 + lm) * ldb + lk;

    const float4 z4 = make_float4(0.f, 0.f, 0.f, 0.f);
    float4 afr[4], bfr[4];
    #pragma unroll
    for (int r = 0; r < 4; r++) {
        int row = lm + 32 * r;
        afr[r] = (bm0 + row < N) ? *(const float4*)(aptr + (long)(32 * r) * lda) : z4;
        bfr[r] = (bn0 + row < O) ? *(const float4*)(bptr + (long)(32 * r) * ldb) : z4;
    }

    // warp tiling: 8 warps -> 2x4, warp tile 64x32
    int w = tid >> 5, lane = tid & 31;
    int wm = (w >> 2) * 64, wn = (w & 3) * 32;
    int g = lane >> 2, t = lane & 3;

    float acc[4][4][4];
    #pragma unroll
    for (int i = 0; i < 4; i++)
        #pragma unroll
        for (int j = 0; j < 4; j++)
            #pragma unroll
            for (int c = 0; c < 4; c++) acc[i][j][c] = 0.f;

    // store regs -> stage st (cvt to tf32 on the way)
    auto store_stage = [&](int st) {
        float* Ab = As + st * MATS_ + lslice * SS_ + lpos;
        float* Bb = Bs + st * MATS_ + lslice * SS_ + lpos;
        #pragma unroll
        for (int r = 0; r < 4; r++) {
            int row = lm + 32 * r;
            float4 ca = make_float4(cvt_tf32(afr[r].x), cvt_tf32(afr[r].y),
                                    cvt_tf32(afr[r].z), cvt_tf32(afr[r].w));
            float4 cb = make_float4(cvt_tf32(bfr[r].x), cvt_tf32(bfr[r].y),
                                    cvt_tf32(bfr[r].z), cvt_tf32(bfr[r].w));
            *(float4*)(Ab + row * 8) = ca;
            *(float4*)(Bb + row * 8) = cb;
        }
    };

    store_stage(0);
    __syncthreads();

    int st = 0;
    for (int k0 = 0; k0 < Keff; k0 += 32) {
        int kn = k0 + 32;
        bool more = kn < Keff;
        if (more) {
            #pragma unroll
            for (int r = 0; r < 4; r++) {
                int row = lm + 32 * r;
                afr[r] = (bm0 + row < N) ? *(const float4*)(aptr + (long)(32 * r) * lda + kn) : z4;
                bfr[r] = (bn0 + row < O) ? *(const float4*)(bptr + (long)(32 * r) * ldb + kn) : z4;
            }
        }

        const float* Ab = As + st * MATS_;
        const float* Bb = Bs + st * MATS_;
        #pragma unroll
        for (int ks = 0; ks < 4; ks++) {
            const float* Aks = Ab + ks * SS_ + 2 * t;
            const float* Bks = Bb + ks * SS_ + 2 * t;
            unsigned a[4][4], bf2[4][2];
            #pragma unroll
            for (int mt = 0; mt < 4; mt++) {
                int r0 = wm + mt * 16 + g;
                float2 lo = *(const float2*)(Aks + r0 * 8);
                float2 hi = *(const float2*)(Aks + (r0 + 8) * 8);
                a[mt][0] = __float_as_uint(lo.x);
                a[mt][1] = __float_as_uint(hi.x);
                a[mt][2] = __float_as_uint(lo.y);
                a[mt][3] = __float_as_uint(hi.y);
            }
            #pragma unroll
            for (int nt = 0; nt < 4; nt++) {
                float2 bv = *(const float2*)(Bks + (wn + nt * 8 + g) * 8);
                bf2[nt][0] = __float_as_uint(bv.x);
                bf2[nt][1] = __float_as_uint(bv.y);
            }
            #pragma unroll
            for (int mt = 0; mt < 4; mt++)
                #pragma unroll
                for (int nt = 0; nt < 4; nt++)
                    mma_tf32(acc[mt][nt], a[mt], bf2[nt]);
        }

        if (more) store_stage(st ^ 1);
        __syncthreads();
        st ^= 1;
    }

    // epilogue
    #pragma unroll
    for (int mt = 0; mt < 4; mt++) {
        #pragma unroll
        for (int hh = 0; hh < 2; hh++) {
            int row = bm0 + wm + mt * 16 + g + hh * 8;
            if (row >= N) continue;
            #pragma unroll
            for (int nt = 0; nt < 4; nt++) {
                int col = bn0 + wn + nt * 8 + 2 * t;
                float v0 = acc[mt][nt][2 * hh] * scale;
                float v1 = acc[mt][nt][2 * hh + 1] * scale;
                if (bias) { v0 += bias[col]; v1 += bias[col + 1]; }
                if (act) {
                    v0 = 0.5f * v0 * (1.f + erff(v0 * 0.70710678118654752f));
                    v1 = 0.5f * v1 * (1.f + erff(v1 * 0.70710678118654752f));
                }
                if (res) {
                    v0 += res[(long)row * ldc + col];
                    v1 += res[(long)row * ldc + col + 1];
                }
                if (col < O)     C[(long)row * ldc + col] = v0;
                if (col + 1 < O) C[(long)row * ldc + col + 1] = v1;
            }
        }
    }
}

// ---------------- causal softmax over score rows ----------------
__global__ __launch_bounds__(128) void softmax_kernel(float* __restrict__ S) {
    int m = blockIdx.x;
    long z = blockIdx.y;
    float* row = S + z * ((long)M_ * SLD_) + (long)m * SLD_;
    int tid = threadIdx.x;
    __shared__ float sb[4];
    float mx = -3.4e38f;
    for (int k = tid; k <= m; k += 128) mx = fmaxf(mx, row[k]);
    #pragma unroll
    for (int o = 16; o; o >>= 1) mx = fmaxf(mx, __shfl_xor_sync(0xffffffffu, mx, o));
    if ((tid & 31) == 0) sb[tid >> 5] = mx;
    __syncthreads();
    mx = fmaxf(fmaxf(sb[0], sb[1]), fmaxf(sb[2], sb[3]));
    __syncthreads();
    float sum = 0.f;
    for (int k = tid; k <= m; k += 128) {
        float e = expf(row[k] - mx);
        row[k] = e;
        sum += e;
    }
    #pragma unroll
    for (int o = 16; o; o >>= 1) sum += __shfl_xor_sync(0xffffffffu, sum, o);
    if ((tid & 31) == 0) sb[tid >> 5] = sum;
    __syncthreads();
    sum = sb[0] + sb[1] + sb[2] + sb[3];
    float inv = 1.f / sum;
    for (int k = tid; k < SLD_; k += 128)
        row[k] = (k <= m) ? row[k] * inv : 0.f;
}

// ---------------- launch ----------------
extern "C" void kernel_launch(void* const* d_in, const int* in_sizes, int n_in,
                              void* d_out, int out_size)
{
    const float* states  = (const float*)d_in[0];
    const int*   actions = (const int*)  d_in[1];
    const float* rtg     = (const float*)d_in[2];
    const int*   tsteps  = (const int*)  d_in[3];
    const float* pe      = (const float*)d_in[4];
    const float* gpe     = (const float*)d_in[5];
    const float* Ws      = (const float*)d_in[6];
    const float* bs      = (const float*)d_in[7];
    const float* Wr      = (const float*)d_in[8];
    const float* br      = (const float*)d_in[9];
    const float* aemb    = (const float*)d_in[10];
    const float* ln1g    = (const float*)d_in[11];
    const float* ln1b    = (const float*)d_in[12];
    const float* Wq      = (const float*)d_in[13];
    const float* bq      = (const float*)d_in[14];
    const float* Wk      = (const float*)d_in[15];
    const float* bk      = (const float*)d_in[16];
    const float* Wv      = (const float*)d_in[17];
    const float* bv      = (const float*)d_in[18];
    const float* Wo      = (const float*)d_in[19];
    const float* bo      = (const float*)d_in[20];
    const float* ln2g    = (const float*)d_in[21];
    const float* ln2b    = (const float*)d_in[22];
    const float* W1      = (const float*)d_in[23];
    const float* b1      = (const float*)d_in[24];
    const float* W2      = (const float*)d_in[25];
    const float* b2      = (const float*)d_in[26];
    const float* lnfg    = (const float*)d_in[27];
    const float* lnfb    = (const float*)d_in[28];
    const float* headW   = (const float*)d_in[29];
    float* out = (float*)d_out;

    float *x, *h, *q, *k, *v, *vt, *y, *ffn, *s, *hf;
    cudaGetSymbolAddress((void**)&x,   g_x);
    cudaGetSymbolAddress((void**)&h,   g_h);
    cudaGetSymbolAddress((void**)&q,   g_q);
    cudaGetSymbolAddress((void**)&k,   g_k);
    cudaGetSymbolAddress((void**)&v,   g_v);
    cudaGetSymbolAddress((void**)&vt,  g_vt);
    cudaGetSymbolAddress((void**)&y,   g_y);
    cudaGetSymbolAddress((void**)&ffn, g_ffn);
    cudaGetSymbolAddress((void**)&s,   g_s);
    cudaGetSymbolAddress((void**)&hf,  g_hf);

    cudaFuncSetAttribute(gemm_tf32, cudaFuncAttributeMaxDynamicSharedMemorySize,
                         GEMM_SMEM_BYTES);

    embed_kernel<<<dim3(M_, B_), 256>>>(states, actions, rtg, tsteps, pe, gpe,
                                        Ws, bs, Wr, br, aemb, x);

    dim3 gden(8, 24, 1);   // 1024/128 x ceil(3068/128)
    const int SB = GEMM_SMEM_BYTES;
    for (int l = 0; l < L_; l++) {
        ln_kernel<<<NR_, 256>>>(x, ln1g + l*D_, ln1b + l*D_, h);

        // fused QKV: z selects W/bias/out
        gemm_tf32<<<dim3(8, 24, 3), 256, SB>>>(h, D_, Wq + (long)l*D_*D_, D_, q, D_,
                                 NR_, D_, D_, bq + l*D_, nullptr, 1.f, 0, 0,
                                 1, 0,0,0,0,0,0,
                                 Wk + (long)l*D_*D_, Wv + (long)l*D_*D_,
                                 bk + l*D_, bv + l*D_, k, v, 1);

        transpose_v<<<dim3(24, 32, B_), 256>>>(v, vt);

        // S = scale * Q K^T per (b,h), causal tile skip
        gemm_tf32<<<dim3(6, 6, B_*H_), 256, SB>>>(q, D_, k, D_, s, SLD_,
                                 M_, M_, DH_, nullptr, nullptr, 0.125f, 0, 1,
                                 H_, (long)M_*D_, DH_, (long)M_*D_, DH_,
                                 (long)H_*M_*SLD_, (long)M_*SLD_,
                                 nullptr, nullptr, nullptr, nullptr, nullptr, nullptr, 0);

        softmax_kernel<<<dim3(M_, B_*H_), 128>>>(s);

        // Y = P @ V : NT with Vt, K truncated per row-tile (mode=2)
        gemm_tf32<<<dim3(1, 6, B_*H_), 256, SB>>>(s, SLD_, vt, SLD_, y, D_,
                                 M_, DH_, SLD_, nullptr, nullptr, 1.f, 0, 2,
                                 H_, (long)H_*M_*SLD_, (long)M_*SLD_,
                                 (long)H_*DH_*SLD_, (long)DH_*SLD_,
                                 (long)M_*D_, (long)DH_,
                                 nullptr, nullptr, nullptr, nullptr, nullptr, nullptr, 0);

        // x += Y Wo^T + bo
        gemm_tf32<<<gden, 256, SB>>>(y, D_, Wo + (long)l*D_*D_, D_, x, D_,
                                 NR_, D_, D_, bo + l*D_, x, 1.f, 0, 0,
                                 1, 0,0,0,0,0,0,
                                 nullptr, nullptr, nullptr, nullptr, nullptr, nullptr, 0);

        ln_kernel<<<NR_, 256>>>(x, ln2g + l*D_, ln2b + l*D_, h);

        // ffn = gelu(h W1^T + b1)
        gemm_tf32<<<dim3(32, 24, 1), 256, SB>>>(h, D_, W1 + (long)l*FF_*D_, D_, ffn, FF_,
                                 NR_, FF_, D_, b1 + l*FF_, nullptr, 1.f, 1, 0,
                                 1, 0,0,0,0,0,0,
                                 nullptr, nullptr, nullptr, nullptr, nullptr, nullptr, 0);
        // x += ffn W2^T + b2
        gemm_tf32<<<gden, 256, SB>>>(ffn, FF_, W2 + (long)l*D_*FF_, FF_, x, D_,
                                 NR_, D_, FF_, b2 + l*D_, x, 1.f, 0, 0,
                                 1, 0,0,0,0,0,0,
                                 nullptr, nullptr, nullptr, nullptr, nullptr, nullptr, 0);
    }

    gatherln_kernel<<<B_*T_, 256>>>(x, lnfg, lnfb, hf);

    // logits = hf @ head_W^T -> [1024, 32000]
    gemm_tf32<<<dim3(250, 8, 1), 256, SB>>>(hf, D_, headW, D_, out, V_,
                                 B_*T_, V_, D_, nullptr, nullptr, 1.f, 0, 0,
                                 1, 0,0,0,0,0,0,
                                 nullptr, nullptr, nullptr, nullptr, nullptr, nullptr, 0);
}

// round 13
// speedup vs baseline: 1.0014x; 1.0014x over previous
#include <cuda_runtime.h>
#include <math.h>

#define B_ 4
#define T_ 256
#define D_ 1024
#define H_ 16
#define DH_ 64
#define L_ 4
#define V_ 32000
#define FF_ 4096
#define M_ 767            // 3*T - 1
#define NR_ (B_*M_)       // 3068
#define SLD_ 768          // padded score row stride

// smem layout constants for gemm: per matrix per stage = 4 k-slices
#define SS_ 1032          // slice stride in floats (128*8 + 8 pad)
#define MATS_ (4*SS_)     // 4128 floats per matrix per stage
#define GEMM_SMEM_BYTES (4*MATS_*4)   // A[2] + B[2] stages = 66048 B

// ---------------- scratch (static device globals; no allocation) ----------------
__device__ float g_x[NR_*D_];
__device__ float g_h[NR_*D_];
__device__ float g_q[NR_*D_];
__device__ float g_k[NR_*D_];
__device__ float g_v[NR_*D_];
__device__ float g_vt[B_*H_*DH_*SLD_];         // V transposed per (b,h): [64][768]
__device__ float g_y[NR_*D_];
__device__ float g_ffn[NR_*FF_];
__device__ float g_s[(size_t)B_*H_*M_*SLD_];   // attention scores/probs
__device__ float g_hf[B_*T_*D_];

// ---------------- helpers ----------------
__device__ __forceinline__ float blockReduceSum256(float val) {
    __shared__ float sb[8];
    int lane = threadIdx.x & 31, wid = threadIdx.x >> 5;
    #pragma unroll
    for (int o = 16; o; o >>= 1) val += __shfl_xor_sync(0xffffffffu, val, o);
    if (lane == 0) sb[wid] = val;
    __syncthreads();
    float r = 0.f;
    #pragma unroll
    for (int i = 0; i < 8; i++) r += sb[i];
    __syncthreads();
    return r;
}

__device__ __forceinline__ float cvt_tf32(float x) {
    float r;
    asm("cvt.rna.tf32.f32 %0, %1;" : "=f"(r) : "f"(x));
    return r;
}

__device__ __forceinline__ void mma_tf32(float* d, const unsigned* a, const unsigned* b) {
    asm volatile(
        "mma.sync.aligned.m16n8k8.row.col.f32.tf32.tf32.f32 "
        "{%0,%1,%2,%3},{%4,%5,%6,%7},{%8,%9},{%0,%1,%2,%3};"
        : "+f"(d[0]), "+f"(d[1]), "+f"(d[2]), "+f"(d[3])
        : "r"(a[0]), "r"(a[1]), "r"(a[2]), "r"(a[3]), "r"(b[0]), "r"(b[1]));
}

// ---------------- embedding ----------------
__global__ __launch_bounds__(256) void embed_kernel(
    const float* __restrict__ states, const int* __restrict__ actions,
    const float* __restrict__ rtg, const int* __restrict__ tsteps,
    const float* __restrict__ pe, const float* __restrict__ gpe,
    const float* __restrict__ Ws, const float* __restrict__ bs,
    const float* __restrict__ Wr, const float* __restrict__ br,
    const float* __restrict__ aemb, float* __restrict__ xout)
{
    int m = blockIdx.x, b = blockIdx.y;
    int i = m / 3, r = m - 3 * i;
    int d = threadIdx.x * 4;
    float t0, t1, t2, t3;
    if (r == 2) {
        long a = actions[b * T_ + i + 1];
        const float* ap = aemb + a * D_ + d;
        t0 = tanhf(ap[0]); t1 = tanhf(ap[1]); t2 = tanhf(ap[2]); t3 = tanhf(ap[3]);
    } else {
        float xval = (r == 0) ? rtg[b * T_ + i] : states[b * T_ + i];
        const float* Wp = (r == 0) ? Wr : Ws;
        const float* bp = (r == 0) ? br : bs;
        t0 = tanhf(xval * Wp[d+0] + bp[d+0]);
        t1 = tanhf(xval * Wp[d+1] + bp[d+1]);
        t2 = tanhf(xval * Wp[d+2] + bp[d+2]);
        t3 = tanhf(xval * Wp[d+3] + bp[d+3]);
    }
    int ts = tsteps[b];
    const float* gp = gpe + (long)ts * D_ + d;
    const float* pp = pe + (long)m * D_ + d;
    float* xp = xout + ((long)b * M_ + m) * D_ + d;
    xp[0] = t0 + gp[0] + pp[0];
    xp[1] = t1 + gp[1] + pp[1];
    xp[2] = t2 + gp[2] + pp[2];
    xp[3] = t3 + gp[3] + pp[3];
}

// ---------------- layernorm ----------------
__global__ __launch_bounds__(256) void ln_kernel(const float* __restrict__ in,
        const float* __restrict__ g, const float* __restrict__ bb,
        float* __restrict__ out)
{
    long row = blockIdx.x;
    int d = threadIdx.x * 4;
    float4 xv = *(const float4*)(in + row * D_ + d);
    float mean = blockReduceSum256(xv.x + xv.y + xv.z + xv.w) * (1.f / D_);
    float a0 = xv.x - mean, a1 = xv.y - mean, a2 = xv.z - mean, a3 = xv.w - mean;
    float var = blockReduceSum256(a0*a0 + a1*a1 + a2*a2 + a3*a3) * (1.f / D_);
    float inv = rsqrtf(var + 1e-5f);
    float4 gv = *(const float4*)(g + d);
    float4 bv = *(const float4*)(bb + d);
    float4 o;
    o.x = a0 * inv * gv.x + bv.x;
    o.y = a1 * inv * gv.y + bv.y;
    o.z = a2 * inv * gv.z + bv.z;
    o.w = a3 * inv * gv.w + bv.w;
    *(float4*)(out + row * D_ + d) = o;
}

__global__ __launch_bounds__(256) void gatherln_kernel(const float* __restrict__ in,
        const float* __restrict__ g, const float* __restrict__ bb,
        float* __restrict__ out)
{
    int n = blockIdx.x;
    int b = n >> 8, i = n & 255;
    long src = ((long)b * M_ + 1 + 3 * i) * D_;
    int d = threadIdx.x * 4;
    float4 xv = *(const float4*)(in + src + d);
    float mean = blockReduceSum256(xv.x + xv.y + xv.z + xv.w) * (1.f / D_);
    float a0 = xv.x - mean, a1 = xv.y - mean, a2 = xv.z - mean, a3 = xv.w - mean;
    float var = blockReduceSum256(a0*a0 + a1*a1 + a2*a2 + a3*a3) * (1.f / D_);
    float inv = rsqrtf(var + 1e-5f);
    float4 gv = *(const float4*)(g + d);
    float4 bv = *(const float4*)(bb + d);
    float4 o;
    o.x = a0 * inv * gv.x + bv.x;
    o.y = a1 * inv * gv.y + bv.y;
    o.z = a2 * inv * gv.z + bv.z;
    o.w = a3 * inv * gv.w + bv.w;
    *(float4*)(out + (long)n * D_ + d) = o;
}

// ---------------- V transpose: V[b][k][h*64+n] -> Vt[(b*H+h)][n][k], k-stride 768 ----------------
__global__ __launch_bounds__(256) void transpose_v(const float* __restrict__ V,
                                                   float* __restrict__ Vt)
{
    __shared__ float tile[32][33];
    int k0 = blockIdx.x * 32, n0 = blockIdx.y * 32, b = blockIdx.z;
    int tx = threadIdx.x & 31, ty = threadIdx.x >> 5;   // 32x8
    #pragma unroll
    for (int i = 0; i < 4; i++) {
        int k = k0 + ty + 8 * i;
        tile[ty + 8 * i][tx] = (k < M_) ? V[((long)b * M_ + k) * D_ + n0 + tx] : 0.f;
    }
    __syncthreads();
    #pragma unroll
    for (int i = 0; i < 4; i++) {
        int n = n0 + ty + 8 * i;
        int h = n >> 6, nn = n & 63;
        int k = k0 + tx;
        if (k < M_)
            Vt[(((long)b * H_ + h) * DH_ + nn) * SLD_ + k] = tile[tx][ty + 8 * i];
    }
}

// ---------------- tf32 tensor-core NT GEMM (double-buffered, k-slice smem) ----------------
// C[n,o] = act(scale * sum_k A[n,k] * B[o,k] + bias[o]) + res
// mode: 0 = plain, 1 = causal tile-skip (QK^T), 2 = K truncated to bm0+128 (PV)
// triple: z in {0,1,2} selects (Bw,bias,C) / (Bw1,bias1,C1) / (Bw2,bias2,C2)
__global__ __launch_bounds__(256, 2) void gemm_tf32(
    const float* __restrict__ A, int lda,
    const float* __restrict__ Bw, int ldb,
    float* __restrict__ C, int ldc,
    int N, int O, int K,
    const float* __restrict__ bias,
    const float* __restrict__ res,
    float scale, int act, int mode,
    int zdiv, long sA1, long sA2, long sB1, long sB2, long sC1, long sC2,
    const float* __restrict__ Bw1, const float* __restrict__ Bw2,
    const float* __restrict__ bias1, const float* __restrict__ bias2,
    float* __restrict__ C1, float* __restrict__ C2, int triple)
{
    extern __shared__ float sm[];
    int bm0 = blockIdx.y * 128;
    int bn0 = blockIdx.x * 128;
    if (mode == 1 && bn0 >= bm0 + 128) return;
    int z = blockIdx.z;
    if (triple) {
        if (z == 1) { Bw = Bw1; bias = bias1; C = C1; }
        else if (z == 2) { Bw = Bw2; bias = bias2; C = C2; }
    } else {
        int zq = z / zdiv, zr = z - zq * zdiv;
        A  += (long)zq * sA1 + (long)zr * sA2;
        Bw += (long)zq * sB1 + (long)zr * sB2;
        long offC = (long)zq * sC1 + (long)zr * sC2;
        C += offC;
        if (res) res += offC;
    }

    int Keff = (mode == 2) ? min(K, bm0 + 128) : K;

    float* As = sm;               // 2 stages x MATS_
    float* Bs = sm + 2 * MATS_;   // 2 stages x MATS_

    int tid = threadIdx.x;
    // loader mapping: 256 threads, 4 float4 per matrix per tile
    int lm = tid >> 3;               // 0..31 (row group)
    int lk = (tid & 7) << 2;         // 0..28 (k offset, 4-aligned)
    int lslice = lk >> 3;            // 0..3
    int lpos   = lk & 7;             // 0 or 4
    const float* aptr = A + (long)(bm0 + lm) * lda + lk;
    const float* bptr = Bw + (long)(bn0 + lm) * ldb + lk;

    const float4 z4 = make_float4(0.f, 0.f, 0.f, 0.f);
    float4 afr[4], bfr[4];
    #pragma unroll
    for (int r = 0; r < 4; r++) {
        int row = lm + 32 * r;
        afr[r] = (bm0 + row < N) ? *(const float4*)(aptr + (long)(32 * r) * lda) : z4;
        bfr[r] = (bn0 + row < O) ? *(const float4*)(bptr + (long)(32 * r) * ldb) : z4;
    }

    // warp tiling: 8 warps -> 2x4, warp tile 64x32
    int w = tid >> 5, lane = tid & 31;
    int wm = (w >> 2) * 64, wn = (w & 3) * 32;
    int g = lane >> 2, t = lane & 3;

    float acc[4][4][4];
    #pragma unroll
    for (int i = 0; i < 4; i++)
        #pragma unroll
        for (int j = 0; j < 4; j++)
            #pragma unroll
            for (int c = 0; c < 4; c++) acc[i][j][c] = 0.f;

    // store regs -> stage st (cvt to tf32 on the way)
    auto store_stage = [&](int st) {
        float* Ab = As + st * MATS_ + lslice * SS_ + lpos;
        float* Bb = Bs + st * MATS_ + lslice * SS_ + lpos;
        #pragma unroll
        for (int r = 0; r < 4; r++) {
            int row = lm + 32 * r;
            float4 ca = make_float4(cvt_tf32(afr[r].x), cvt_tf32(afr[r].y),
                                    cvt_tf32(afr[r].z), cvt_tf32(afr[r].w));
            float4 cb = make_float4(cvt_tf32(bfr[r].x), cvt_tf32(bfr[r].y),
                                    cvt_tf32(bfr[r].z), cvt_tf32(bfr[r].w));
            *(float4*)(Ab + row * 8) = ca;
            *(float4*)(Bb + row * 8) = cb;
        }
    };

    store_stage(0);
    __syncthreads();

    int st = 0;
    for (int k0 = 0; k0 < Keff; k0 += 32) {
        int kn = k0 + 32;
        bool more = kn < Keff;
        if (more) {
            #pragma unroll
            for (int r = 0; r < 4; r++) {
                int row = lm + 32 * r;
                afr[r] = (bm0 + row < N) ? *(const float4*)(aptr + (long)(32 * r) * lda + kn) : z4;
                bfr[r] = (bn0 + row < O) ? *(const float4*)(bptr + (long)(32 * r) * ldb + kn) : z4;
            }
        }

        const float* Ab = As + st * MATS_;
        const float* Bb = Bs + st * MATS_;
        #pragma unroll
        for (int ks = 0; ks < 4; ks++) {
            const float* Aks = Ab + ks * SS_ + 2 * t;
            const float* Bks = Bb + ks * SS_ + 2 * t;
            unsigned a[4][4], bf2[4][2];
            #pragma unroll
            for (int mt = 0; mt < 4; mt++) {
                int r0 = wm + mt * 16 + g;
                float2 lo = *(const float2*)(Aks + r0 * 8);
                float2 hi = *(const float2*)(Aks + (r0 + 8) * 8);
                a[mt][0] = __float_as_uint(lo.x);
                a[mt][1] = __float_as_uint(hi.x);
                a[mt][2] = __float_as_uint(lo.y);
                a[mt][3] = __float_as_uint(hi.y);
            }
            #pragma unroll
            for (int nt = 0; nt < 4; nt++) {
                float2 bv = *(const float2*)(Bks + (wn + nt * 8 + g) * 8);
                bf2[nt][0] = __float_as_uint(bv.x);
                bf2[nt][1] = __float_as_uint(bv.y);
            }
            #pragma unroll
            for (int mt = 0; mt < 4; mt++)
                #pragma unroll
                for (int nt = 0; nt < 4; nt++)
                    mma_tf32(acc[mt][nt], a[mt], bf2[nt]);
        }

        if (more) store_stage(st ^ 1);
        __syncthreads();
        st ^= 1;
    }

    // epilogue
    #pragma unroll
    for (int mt = 0; mt < 4; mt++) {
        #pragma unroll
        for (int hh = 0; hh < 2; hh++) {
            int row = bm0 + wm + mt * 16 + g + hh * 8;
            if (row >= N) continue;
            #pragma unroll
            for (int nt = 0; nt < 4; nt++) {
                int col = bn0 + wn + nt * 8 + 2 * t;
                float v0 = acc[mt][nt][2 * hh] * scale;
                float v1 = acc[mt][nt][2 * hh + 1] * scale;
                if (bias) { v0 += bias[col]; v1 += bias[col + 1]; }
                if (act) {
                    v0 = 0.5f * v0 * (1.f + erff(v0 * 0.70710678118654752f));
                    v1 = 0.5f * v1 * (1.f + erff(v1 * 0.70710678118654752f));
                }
                if (res) {
                    v0 += res[(long)row * ldc + col];
                    v1 += res[(long)row * ldc + col + 1];
                }
                if (col < O)     C[(long)row * ldc + col] = v0;
                if (col + 1 < O) C[(long)row * ldc + col + 1] = v1;
            }
        }
    }
}

// ---------------- causal softmax over score rows ----------------
__global__ __launch_bounds__(128) void softmax_kernel(float* __restrict__ S) {
    int m = blockIdx.x;
    long z = blockIdx.y;
    float* row = S + z * ((long)M_ * SLD_) + (long)m * SLD_;
    int tid = threadIdx.x;
    __shared__ float sb[4];
    float mx = -3.4e38f;
    for (int k = tid; k <= m; k += 128) mx = fmaxf(mx, row[k]);
    #pragma unroll
    for (int o = 16; o; o >>= 1) mx = fmaxf(mx, __shfl_xor_sync(0xffffffffu, mx, o));
    if ((tid & 31) == 0) sb[tid >> 5] = mx;
    __syncthreads();
    mx = fmaxf(fmaxf(sb[0], sb[1]), fmaxf(sb[2], sb[3]));
    __syncthreads();
    float sum = 0.f;
    for (int k = tid; k <= m; k += 128) {
        float e = expf(row[k] - mx);
        row[k] = e;
        sum += e;
    }
    #pragma unroll
    for (int o = 16; o; o >>= 1) sum += __shfl_xor_sync(0xffffffffu, sum, o);
    if ((tid & 31) == 0) sb[tid >> 5] = sum;
    __syncthreads();
    sum = sb[0] + sb[1] + sb[2] + sb[3];
    float inv = 1.f / sum;
    for (int k = tid; k < SLD_; k += 128)
        row[k] = (k <= m) ? row[k] * inv : 0.f;
}

// ---------------- launch ----------------
extern "C" void kernel_launch(void* const* d_in, const int* in_sizes, int n_in,
                              void* d_out, int out_size)
{
    const float* states  = (const float*)d_in[0];
    const int*   actions = (const int*)  d_in[1];
    const float* rtg     = (const float*)d_in[2];
    const int*   tsteps  = (const int*)  d_in[3];
    const float* pe      = (const float*)d_in[4];
    const float* gpe     = (const float*)d_in[5];
    const float* Ws      = (const float*)d_in[6];
    const float* bs      = (const float*)d_in[7];
    const float* Wr      = (const float*)d_in[8];
    const float* br      = (const float*)d_in[9];
    const float* aemb    = (const float*)d_in[10];
    const float* ln1g    = (const float*)d_in[11];
    const float* ln1b    = (const float*)d_in[12];
    const float* Wq      = (const float*)d_in[13];
    const float* bq      = (const float*)d_in[14];
    const float* Wk      = (const float*)d_in[15];
    const float* bk      = (const float*)d_in[16];
    const float* Wv      = (const float*)d_in[17];
    const float* bv      = (const float*)d_in[18];
    const float* Wo      = (const float*)d_in[19];
    const float* bo      = (const float*)d_in[20];
    const float* ln2g    = (const float*)d_in[21];
    const float* ln2b    = (const float*)d_in[22];
    const float* W1      = (const float*)d_in[23];
    const float* b1      = (const float*)d_in[24];
    const float* W2      = (const float*)d_in[25];
    const float* b2      = (const float*)d_in[26];
    const float* lnfg    = (const float*)d_in[27];
    const float* lnfb    = (const float*)d_in[28];
    const float* headW   = (const float*)d_in[29];
    float* out = (float*)d_out;

    float *x, *h, *q, *k, *v, *vt, *y, *ffn, *s, *hf;
    cudaGetSymbolAddress((void**)&x,   g_x);
    cudaGetSymbolAddress((void**)&h,   g_h);
    cudaGetSymbolAddress((void**)&q,   g_q);
    cudaGetSymbolAddress((void**)&k,   g_k);
    cudaGetSymbolAddress((void**)&v,   g_v);
    cudaGetSymbolAddress((void**)&vt,  g_vt);
    cudaGetSymbolAddress((void**)&y,   g_y);
    cudaGetSymbolAddress((void**)&ffn, g_ffn);
    cudaGetSymbolAddress((void**)&s,   g_s);
    cudaGetSymbolAddress((void**)&hf,  g_hf);

    cudaFuncSetAttribute(gemm_tf32, cudaFuncAttributeMaxDynamicSharedMemorySize,
                         GEMM_SMEM_BYTES);

    embed_kernel<<<dim3(M_, B_), 256>>>(states, actions, rtg, tsteps, pe, gpe,
                                        Ws, bs, Wr, br, aemb, x);

    dim3 gden(8, 24, 1);   // 1024/128 x ceil(3068/128)
    const int SB = GEMM_SMEM_BYTES;
    for (int l = 0; l < L_; l++) {
        ln_kernel<<<NR_, 256>>>(x, ln1g + l*D_, ln1b + l*D_, h);

        // fused QKV: z selects W/bias/out
        gemm_tf32<<<dim3(8, 24, 3), 256, SB>>>(h, D_, Wq + (long)l*D_*D_, D_, q, D_,
                                 NR_, D_, D_, bq + l*D_, nullptr, 1.f, 0, 0,
                                 1, 0,0,0,0,0,0,
                                 Wk + (long)l*D_*D_, Wv + (long)l*D_*D_,
                                 bk + l*D_, bv + l*D_, k, v, 1);

        transpose_v<<<dim3(24, 32, B_), 256>>>(v, vt);

        // S = scale * Q K^T per (b,h), causal tile skip
        gemm_tf32<<<dim3(6, 6, B_*H_), 256, SB>>>(q, D_, k, D_, s, SLD_,
                                 M_, M_, DH_, nullptr, nullptr, 0.125f, 0, 1,
                                 H_, (long)M_*D_, DH_, (long)M_*D_, DH_,
                                 (long)H_*M_*SLD_, (long)M_*SLD_,
                                 nullptr, nullptr, nullptr, nullptr, nullptr, nullptr, 0);

        softmax_kernel<<<dim3(M_, B_*H_), 128>>>(s);

        // Y = P @ V : NT with Vt, K truncated per row-tile (mode=2)
        gemm_tf32<<<dim3(1, 6, B_*H_), 256, SB>>>(s, SLD_, vt, SLD_, y, D_,
                                 M_, DH_, SLD_, nullptr, nullptr, 1.f, 0, 2,
                                 H_, (long)H_*M_*SLD_, (long)M_*SLD_,
                                 (long)H_*DH_*SLD_, (long)DH_*SLD_,
                                 (long)M_*D_, (long)DH_,
                                 nullptr, nullptr, nullptr, nullptr, nullptr, nullptr, 0);

        // x += Y Wo^T + bo
        gemm_tf32<<<gden, 256, SB>>>(y, D_, Wo + (long)l*D_*D_, D_, x, D_,
                                 NR_, D_, D_, bo + l*D_, x, 1.f, 0, 0,
                                 1, 0,0,0,0,0,0,
                                 nullptr, nullptr, nullptr, nullptr, nullptr, nullptr, 0);

        ln_kernel<<<NR_, 256>>>(x, ln2g + l*D_, ln2b + l*D_, h);

        // ffn = gelu(h W1^T + b1)
        gemm_tf32<<<dim3(32, 24, 1), 256, SB>>>(h, D_, W1 + (long)l*FF_*D_, D_, ffn, FF_,
                                 NR_, FF_, D_, b1 + l*FF_, nullptr, 1.f, 1, 0,
                                 1, 0,0,0,0,0,0,
                                 nullptr, nullptr, nullptr, nullptr, nullptr, nullptr, 0);
        // x += ffn W2^T + b2
        gemm_tf32<<<gden, 256, SB>>>(ffn, FF_, W2 + (long)l*D_*FF_, FF_, x, D_,
                                 NR_, D_, FF_, b2 + l*D_, x, 1.f, 0, 0,
                                 1, 0,0,0,0,0,0,
                                 nullptr, nullptr, nullptr, nullptr, nullptr, nullptr, 0);
    }

    gatherln_kernel<<<B_*T_, 256>>>(x, lnfg, lnfb, hf);

    // logits = hf @ head_W^T -> [1024, 32000]
    gemm_tf32<<<dim3(250, 8, 1), 256, SB>>>(hf, D_, headW, D_, out, V_,
                                 B_*T_, V_, D_, nullptr, nullptr, 1.f, 0, 0,
                                 1, 0,0,0,0,0,0,
                                 nullptr, nullptr, nullptr, nullptr, nullptr, nullptr, 0);
}

// round 14
// speedup vs baseline: 1.0034x; 1.0020x over previous
#include <cuda_runtime.h>
#include <math.h>

#define B_ 4
#define T_ 256
#define D_ 1024
#define H_ 16
#define DH_ 64
#define L_ 4
#define V_ 32000
#define FF_ 4096
#define M_ 767            // 3*T - 1
#define NR_ (B_*M_)       // 3068
#define SLD_ 768          // padded score row stride

// smem layout constants for gemm: per matrix per stage = 4 k-slices
#define SS_ 1032          // slice stride in floats (128*8 + 8 pad)
#define MATS_ (4*SS_)     // 4128 floats per matrix per stage
#define GEMM_SMEM_BYTES (4*MATS_*4)   // A[2] + B[2] stages = 66048 B

// ---------------- scratch (static device globals; no allocation) ----------------
__device__ float g_x[NR_*D_];
__device__ float g_h[NR_*D_];
__device__ float g_q[NR_*D_];
__device__ float g_k[NR_*D_];
__device__ float g_v[NR_*D_];
__device__ float g_vt[B_*H_*DH_*SLD_];         // V transposed per (b,h): [64][768]
__device__ float g_y[NR_*D_];
__device__ float g_ffn[NR_*FF_];
__device__ float g_s[(size_t)B_*H_*M_*SLD_];   // attention scores/probs
__device__ float g_hf[B_*T_*D_];

// ---------------- helpers ----------------
__device__ __forceinline__ float blockReduceSum256(float val) {
    __shared__ float sb[8];
    int lane = threadIdx.x & 31, wid = threadIdx.x >> 5;
    #pragma unroll
    for (int o = 16; o; o >>= 1) val += __shfl_xor_sync(0xffffffffu, val, o);
    if (lane == 0) sb[wid] = val;
    __syncthreads();
    float r = 0.f;
    #pragma unroll
    for (int i = 0; i < 8; i++) r += sb[i];
    __syncthreads();
    return r;
}

__device__ __forceinline__ float cvt_tf32(float x) {
    float r;
    asm("cvt.rna.tf32.f32 %0, %1;" : "=f"(r) : "f"(x));
    return r;
}

__device__ __forceinline__ void mma_tf32(float* d, const unsigned* a, const unsigned* b) {
    asm volatile(
        "mma.sync.aligned.m16n8k8.row.col.f32.tf32.tf32.f32 "
        "{%0,%1,%2,%3},{%4,%5,%6,%7},{%8,%9},{%0,%1,%2,%3};"
        : "+f"(d[0]), "+f"(d[1]), "+f"(d[2]), "+f"(d[3])
        : "r"(a[0]), "r"(a[1]), "r"(a[2]), "r"(a[3]), "r"(b[0]), "r"(b[1]));
}

// ---------------- embedding ----------------
__global__ __launch_bounds__(256) void embed_kernel(
    const float* __restrict__ states, const int* __restrict__ actions,
    const float* __restrict__ rtg, const int* __restrict__ tsteps,
    const float* __restrict__ pe, const float* __restrict__ gpe,
    const float* __restrict__ Ws, const float* __restrict__ bs,
    const float* __restrict__ Wr, const float* __restrict__ br,
    const float* __restrict__ aemb, float* __restrict__ xout)
{
    int m = blockIdx.x, b = blockIdx.y;
    int i = m / 3, r = m - 3 * i;
    int d = threadIdx.x * 4;
    float t0, t1, t2, t3;
    if (r == 2) {
        long a = actions[b * T_ + i + 1];
        const float* ap = aemb + a * D_ + d;
        t0 = tanhf(ap[0]); t1 = tanhf(ap[1]); t2 = tanhf(ap[2]); t3 = tanhf(ap[3]);
    } else {
        float xval = (r == 0) ? rtg[b * T_ + i] : states[b * T_ + i];
        const float* Wp = (r == 0) ? Wr : Ws;
        const float* bp = (r == 0) ? br : bs;
        t0 = tanhf(xval * Wp[d+0] + bp[d+0]);
        t1 = tanhf(xval * Wp[d+1] + bp[d+1]);
        t2 = tanhf(xval * Wp[d+2] + bp[d+2]);
        t3 = tanhf(xval * Wp[d+3] + bp[d+3]);
    }
    int ts = tsteps[b];
    const float* gp = gpe + (long)ts * D_ + d;
    const float* pp = pe + (long)m * D_ + d;
    float* xp = xout + ((long)b * M_ + m) * D_ + d;
    xp[0] = t0 + gp[0] + pp[0];
    xp[1] = t1 + gp[1] + pp[1];
    xp[2] = t2 + gp[2] + pp[2];
    xp[3] = t3 + gp[3] + pp[3];
}

// ---------------- layernorm ----------------
__global__ __launch_bounds__(256) void ln_kernel(const float* __restrict__ in,
        const float* __restrict__ g, const float* __restrict__ bb,
        float* __restrict__ out)
{
    long row = blockIdx.x;
    int d = threadIdx.x * 4;
    float4 xv = *(const float4*)(in + row * D_ + d);
    float mean = blockReduceSum256(xv.x + xv.y + xv.z + xv.w) * (1.f / D_);
    float a0 = xv.x - mean, a1 = xv.y - mean, a2 = xv.z - mean, a3 = xv.w - mean;
    float var = blockReduceSum256(a0*a0 + a1*a1 + a2*a2 + a3*a3) * (1.f / D_);
    float inv = rsqrtf(var + 1e-5f);
    float4 gv = *(const float4*)(g + d);
    float4 bv = *(const float4*)(bb + d);
    float4 o;
    o.x = a0 * inv * gv.x + bv.x;
    o.y = a1 * inv * gv.y + bv.y;
    o.z = a2 * inv * gv.z + bv.z;
    o.w = a3 * inv * gv.w + bv.w;
    *(float4*)(out + row * D_ + d) = o;
}

__global__ __launch_bounds__(256) void gatherln_kernel(const float* __restrict__ in,
        const float* __restrict__ g, const float* __restrict__ bb,
        float* __restrict__ out)
{
    int n = blockIdx.x;
    int b = n >> 8, i = n & 255;
    long src = ((long)b * M_ + 1 + 3 * i) * D_;
    int d = threadIdx.x * 4;
    float4 xv = *(const float4*)(in + src + d);
    float mean = blockReduceSum256(xv.x + xv.y + xv.z + xv.w) * (1.f / D_);
    float a0 = xv.x - mean, a1 = xv.y - mean, a2 = xv.z - mean, a3 = xv.w - mean;
    float var = blockReduceSum256(a0*a0 + a1*a1 + a2*a2 + a3*a3) * (1.f / D_);
    float inv = rsqrtf(var + 1e-5f);
    float4 gv = *(const float4*)(g + d);
    float4 bv = *(const float4*)(bb + d);
    float4 o;
    o.x = a0 * inv * gv.x + bv.x;
    o.y = a1 * inv * gv.y + bv.y;
    o.z = a2 * inv * gv.z + bv.z;
    o.w = a3 * inv * gv.w + bv.w;
    *(float4*)(out + (long)n * D_ + d) = o;
}

// ---------------- V transpose: V[b][k][h*64+n] -> Vt[(b*H+h)][n][k], k-stride 768 ----------------
__global__ __launch_bounds__(256) void transpose_v(const float* __restrict__ V,
                                                   float* __restrict__ Vt)
{
    __shared__ float tile[32][33];
    int k0 = blockIdx.x * 32, n0 = blockIdx.y * 32, b = blockIdx.z;
    int tx = threadIdx.x & 31, ty = threadIdx.x >> 5;   // 32x8
    #pragma unroll
    for (int i = 0; i < 4; i++) {
        int k = k0 + ty + 8 * i;
        tile[ty + 8 * i][tx] = (k < M_) ? V[((long)b * M_ + k) * D_ + n0 + tx] : 0.f;
    }
    __syncthreads();
    #pragma unroll
    for (int i = 0; i < 4; i++) {
        int n = n0 + ty + 8 * i;
        int h = n >> 6, nn = n & 63;
        int k = k0 + tx;
        if (k < M_)
            Vt[(((long)b * H_ + h) * DH_ + nn) * SLD_ + k] = tile[tx][ty + 8 * i];
    }
}

// ---------------- tf32 tensor-core NT GEMM (double-buffered, k-slice smem) ----------------
// C[n,o] = act(scale * sum_k A[n,k] * B[o,k] + bias[o]) + res
// mode: 0 = plain, 1 = causal tile-skip (QK^T), 2 = K truncated to bm0+128 (PV)
// triple: z in {0,1,2} selects (Bw,bias,C) / (Bw1,bias1,C1) / (Bw2,bias2,C2)
__global__ __launch_bounds__(256, 2) void gemm_tf32(
    const float* __restrict__ A, int lda,
    const float* __restrict__ Bw, int ldb,
    float* __restrict__ C, int ldc,
    int N, int O, int K,
    const float* __restrict__ bias,
    const float* __restrict__ res,
    float scale, int act, int mode,
    int zdiv, long sA1, long sA2, long sB1, long sB2, long sC1, long sC2,
    const float* __restrict__ Bw1, const float* __restrict__ Bw2,
    const float* __restrict__ bias1, const float* __restrict__ bias2,
    float* __restrict__ C1, float* __restrict__ C2, int triple)
{
    extern __shared__ float sm[];
    int bm0 = blockIdx.y * 128;
    int bn0 = blockIdx.x * 128;
    if (mode == 1 && bn0 >= bm0 + 128) return;
    int z = blockIdx.z;
    if (triple) {
        if (z == 1) { Bw = Bw1; bias = bias1; C = C1; }
        else if (z == 2) { Bw = Bw2; bias = bias2; C = C2; }
    } else {
        int zq = z / zdiv, zr = z - zq * zdiv;
        A  += (long)zq * sA1 + (long)zr * sA2;
        Bw += (long)zq * sB1 + (long)zr * sB2;
        long offC = (long)zq * sC1 + (long)zr * sC2;
        C += offC;
        if (res) res += offC;
    }

    int Keff = (mode == 2) ? min(K, bm0 + 128) : K;

    float* As = sm;               // 2 stages x MATS_
    float* Bs = sm + 2 * MATS_;   // 2 stages x MATS_

    int tid = threadIdx.x;
    // loader mapping: 256 threads, 4 float4 per matrix per tile
    int lm = tid >> 3;               // 0..31 (row group)
    int lk = (tid & 7) << 2;         // 0..28 (k offset, 4-aligned)
    int lslice = lk >> 3;            // 0..3
    int lpos   = lk & 7;             // 0 or 4
    const float* aptr = A + (long)(bm0 + lm) * lda + lk;
    const float* bptr = Bw + (long)(bn0 + lm) * ldb + lk;

    const float4 z4 = make_float4(0.f, 0.f, 0.f, 0.f);
    float4 afr[4], bfr[4];
    #pragma unroll
    for (int r = 0; r < 4; r++) {
        int row = lm + 32 * r;
        afr[r] = (bm0 + row < N) ? *(const float4*)(aptr + (long)(32 * r) * lda) : z4;
        bfr[r] = (bn0 + row < O) ? *(const float4*)(bptr + (long)(32 * r) * ldb) : z4;
    }

    // warp tiling: 8 warps -> 2x4, warp tile 64x32
    int w = tid >> 5, lane = tid & 31;
    int wm = (w >> 2) * 64, wn = (w & 3) * 32;
    int g = lane >> 2, t = lane & 3;

    float acc[4][4][4];
    #pragma unroll
    for (int i = 0; i < 4; i++)
        #pragma unroll
        for (int j = 0; j < 4; j++)
            #pragma unroll
            for (int c = 0; c < 4; c++) acc[i][j][c] = 0.f;

    // store regs -> stage st (cvt to tf32 on the way)
    auto store_stage = [&](int st) {
        float* Ab = As + st * MATS_ + lslice * SS_ + lpos;
        float* Bb = Bs + st * MATS_ + lslice * SS_ + lpos;
        #pragma unroll
        for (int r = 0; r < 4; r++) {
            int row = lm + 32 * r;
            float4 ca = make_float4(cvt_tf32(afr[r].x), cvt_tf32(afr[r].y),
                                    cvt_tf32(afr[r].z), cvt_tf32(afr[r].w));
            float4 cb = make_float4(cvt_tf32(bfr[r].x), cvt_tf32(bfr[r].y),
                                    cvt_tf32(bfr[r].z), cvt_tf32(bfr[r].w));
            *(float4*)(Ab + row * 8) = ca;
            *(float4*)(Bb + row * 8) = cb;
        }
    };

    store_stage(0);
    __syncthreads();

    int st = 0;
    for (int k0 = 0; k0 < Keff; k0 += 32) {
        int kn = k0 + 32;
        bool more = kn < Keff;
        if (more) {
            #pragma unroll
            for (int r = 0; r < 4; r++) {
                int row = lm + 32 * r;
                afr[r] = (bm0 + row < N) ? *(const float4*)(aptr + (long)(32 * r) * lda + kn) : z4;
                bfr[r] = (bn0 + row < O) ? *(const float4*)(bptr + (long)(32 * r) * ldb + kn) : z4;
            }
        }

        const float* Ab = As + st * MATS_;
        const float* Bb = Bs + st * MATS_;
        #pragma unroll
        for (int ks = 0; ks < 4; ks++) {
            const float* Aks = Ab + ks * SS_ + 2 * t;
            const float* Bks = Bb + ks * SS_ + 2 * t;
            unsigned a[4][4], bf2[4][2];
            #pragma unroll
            for (int mt = 0; mt < 4; mt++) {
                int r0 = wm + mt * 16 + g;
                float2 lo = *(const float2*)(Aks + r0 * 8);
                float2 hi = *(const float2*)(Aks + (r0 + 8) * 8);
                a[mt][0] = __float_as_uint(lo.x);
                a[mt][1] = __float_as_uint(hi.x);
                a[mt][2] = __float_as_uint(lo.y);
                a[mt][3] = __float_as_uint(hi.y);
            }
            #pragma unroll
            for (int nt = 0; nt < 4; nt++) {
                float2 bv = *(const float2*)(Bks + (wn + nt * 8 + g) * 8);
                bf2[nt][0] = __float_as_uint(bv.x);
                bf2[nt][1] = __float_as_uint(bv.y);
            }
            #pragma unroll
            for (int mt = 0; mt < 4; mt++)
                #pragma unroll
                for (int nt = 0; nt < 4; nt++)
                    mma_tf32(acc[mt][nt], a[mt], bf2[nt]);
        }

        if (more) store_stage(st ^ 1);
        __syncthreads();
        st ^= 1;
    }

    // epilogue
    #pragma unroll
    for (int mt = 0; mt < 4; mt++) {
        #pragma unroll
        for (int hh = 0; hh < 2; hh++) {
            int row = bm0 + wm + mt * 16 + g + hh * 8;
            if (row >= N) continue;
            #pragma unroll
            for (int nt = 0; nt < 4; nt++) {
                int col = bn0 + wn + nt * 8 + 2 * t;
                float v0 = acc[mt][nt][2 * hh] * scale;
                float v1 = acc[mt][nt][2 * hh + 1] * scale;
                if (bias) { v0 += bias[col]; v1 += bias[col + 1]; }
                if (act) {
                    v0 = 0.5f * v0 * (1.f + erff(v0 * 0.70710678118654752f));
                    v1 = 0.5f * v1 * (1.f + erff(v1 * 0.70710678118654752f));
                }
                if (res) {
                    v0 += res[(long)row * ldc + col];
                    v1 += res[(long)row * ldc + col + 1];
                }
                if (col < O)     C[(long)row * ldc + col] = v0;
                if (col + 1 < O) C[(long)row * ldc + col + 1] = v1;
            }
        }
    }
}

// ---------------- causal softmax over score rows ----------------
__global__ __launch_bounds__(128) void softmax_kernel(float* __restrict__ S) {
    int m = blockIdx.x;
    long z = blockIdx.y;
    float* row = S + z * ((long)M_ * SLD_) + (long)m * SLD_;
    int tid = threadIdx.x;
    __shared__ float sb[4];
    float mx = -3.4e38f;
    for (int k = tid; k <= m; k += 128) mx = fmaxf(mx, row[k]);
    #pragma unroll
    for (int o = 16; o; o >>= 1) mx = fmaxf(mx, __shfl_xor_sync(0xffffffffu, mx, o));
    if ((tid & 31) == 0) sb[tid >> 5] = mx;
    __syncthreads();
    mx = fmaxf(fmaxf(sb[0], sb[1]), fmaxf(sb[2], sb[3]));
    __syncthreads();
    float sum = 0.f;
    for (int k = tid; k <= m; k += 128) {
        float e = expf(row[k] - mx);
        row[k] = e;
        sum += e;
    }
    #pragma unroll
    for (int o = 16; o; o >>= 1) sum += __shfl_xor_sync(0xffffffffu, sum, o);
    if ((tid & 31) == 0) sb[tid >> 5] = sum;
    __syncthreads();
    sum = sb[0] + sb[1] + sb[2] + sb[3];
    float inv = 1.f / sum;
    for (int k = tid; k < SLD_; k += 128)
        row[k] = (k <= m) ? row[k] * inv : 0.f;
}

// ---------------- launch ----------------
extern "C" void kernel_launch(void* const* d_in, const int* in_sizes, int n_in,
                              void* d_out, int out_size)
{
    const float* states  = (const float*)d_in[0];
    const int*   actions = (const int*)  d_in[1];
    const float* rtg     = (const float*)d_in[2];
    const int*   tsteps  = (const int*)  d_in[3];
    const float* pe      = (const float*)d_in[4];
    const float* gpe     = (const float*)d_in[5];
    const float* Ws      = (const float*)d_in[6];
    const float* bs      = (const float*)d_in[7];
    const float* Wr      = (const float*)d_in[8];
    const float* br      = (const float*)d_in[9];
    const float* aemb    = (const float*)d_in[10];
    const float* ln1g    = (const float*)d_in[11];
    const float* ln1b    = (const float*)d_in[12];
    const float* Wq      = (const float*)d_in[13];
    const float* bq      = (const float*)d_in[14];
    const float* Wk      = (const float*)d_in[15];
    const float* bk      = (const float*)d_in[16];
    const float* Wv      = (const float*)d_in[17];
    const float* bv      = (const float*)d_in[18];
    const float* Wo      = (const float*)d_in[19];
    const float* bo      = (const float*)d_in[20];
    const float* ln2g    = (const float*)d_in[21];
    const float* ln2b    = (const float*)d_in[22];
    const float* W1      = (const float*)d_in[23];
    const float* b1      = (const float*)d_in[24];
    const float* W2      = (const float*)d_in[25];
    const float* b2      = (const float*)d_in[26];
    const float* lnfg    = (const float*)d_in[27];
    const float* lnfb    = (const float*)d_in[28];
    const float* headW   = (const float*)d_in[29];
    float* out = (float*)d_out;

    float *x, *h, *q, *k, *v, *vt, *y, *ffn, *s, *hf;
    cudaGetSymbolAddress((void**)&x,   g_x);
    cudaGetSymbolAddress((void**)&h,   g_h);
    cudaGetSymbolAddress((void**)&q,   g_q);
    cudaGetSymbolAddress((void**)&k,   g_k);
    cudaGetSymbolAddress((void**)&v,   g_v);
    cudaGetSymbolAddress((void**)&vt,  g_vt);
    cudaGetSymbolAddress((void**)&y,   g_y);
    cudaGetSymbolAddress((void**)&ffn, g_ffn);
    cudaGetSymbolAddress((void**)&s,   g_s);
    cudaGetSymbolAddress((void**)&hf,  g_hf);

    cudaFuncSetAttribute(gemm_tf32, cudaFuncAttributeMaxDynamicSharedMemorySize,
                         GEMM_SMEM_BYTES);

    embed_kernel<<<dim3(M_, B_), 256>>>(states, actions, rtg, tsteps, pe, gpe,
                                        Ws, bs, Wr, br, aemb, x);

    dim3 gden(8, 24, 1);   // 1024/128 x ceil(3068/128)
    const int SB = GEMM_SMEM_BYTES;
    for (int l = 0; l < L_; l++) {
        ln_kernel<<<NR_, 256>>>(x, ln1g + l*D_, ln1b + l*D_, h);

        // fused QKV: z selects W/bias/out
        gemm_tf32<<<dim3(8, 24, 3), 256, SB>>>(h, D_, Wq + (long)l*D_*D_, D_, q, D_,
                                 NR_, D_, D_, bq + l*D_, nullptr, 1.f, 0, 0,
                                 1, 0,0,0,0,0,0,
                                 Wk + (long)l*D_*D_, Wv + (long)l*D_*D_,
                                 bk + l*D_, bv + l*D_, k, v, 1);

        transpose_v<<<dim3(24, 32, B_), 256>>>(v, vt);

        // S = scale * Q K^T per (b,h), causal tile skip
        gemm_tf32<<<dim3(6, 6, B_*H_), 256, SB>>>(q, D_, k, D_, s, SLD_,
                                 M_, M_, DH_, nullptr, nullptr, 0.125f, 0, 1,
                                 H_, (long)M_*D_, DH_, (long)M_*D_, DH_,
                                 (long)H_*M_*SLD_, (long)M_*SLD_,
                                 nullptr, nullptr, nullptr, nullptr, nullptr, nullptr, 0);

        softmax_kernel<<<dim3(M_, B_*H_), 128>>>(s);

        // Y = P @ V : NT with Vt, K truncated per row-tile (mode=2)
        gemm_tf32<<<dim3(1, 6, B_*H_), 256, SB>>>(s, SLD_, vt, SLD_, y, D_,
                                 M_, DH_, SLD_, nullptr, nullptr, 1.f, 0, 2,
                                 H_, (long)H_*M_*SLD_, (long)M_*SLD_,
                                 (long)H_*DH_*SLD_, (long)DH_*SLD_,
                                 (long)M_*D_, (long)DH_,
                                 nullptr, nullptr, nullptr, nullptr, nullptr, nullptr, 0);

        // x += Y Wo^T + bo
        gemm_tf32<<<gden, 256, SB>>>(y, D_, Wo + (long)l*D_*D_, D_, x, D_,
                                 NR_, D_, D_, bo + l*D_, x, 1.f, 0, 0,
                                 1, 0,0,0,0,0,0,
                                 nullptr, nullptr, nullptr, nullptr, nullptr, nullptr, 0);

        ln_kernel<<<NR_, 256>>>(x, ln2g + l*D_, ln2b + l*D_, h);

        // ffn = gelu(h W1^T + b1)
        gemm_tf32<<<dim3(32, 24, 1), 256, SB>>>(h, D_, W1 + (long)l*FF_*D_, D_, ffn, FF_,
                                 NR_, FF_, D_, b1 + l*FF_, nullptr, 1.f, 1, 0,
                                 1, 0,0,0,0,0,0,
                                 nullptr, nullptr, nullptr, nullptr, nullptr, nullptr, 0);
        // x += ffn W2^T + b2
        gemm_tf32<<<gden, 256, SB>>>(ffn, FF_, W2 + (long)l*D_*FF_, FF_, x, D_,
                                 NR_, D_, FF_, b2 + l*D_, x, 1.f, 0, 0,
                                 1, 0,0,0,0,0,0,
                                 nullptr, nullptr, nullptr, nullptr, nullptr, nullptr, 0);
    }

    gatherln_kernel<<<B_*T_, 256>>>(x, lnfg, lnfb, hf);

    // logits = hf @ head_W^T -> [1024, 32000]
    gemm_tf32<<<dim3(250, 8, 1), 256, SB>>>(hf, D_, headW, D_, out, V_,
                                 B_*T_, V_, D_, nullptr, nullptr, 1.f, 0, 0,
                                 1, 0,0,0,0,0,0,
                                 nullptr, nullptr, nullptr, nullptr, nullptr, nullptr, 0);
}